// round 1
// baseline (speedup 1.0000x reference)
#include <cuda_runtime.h>

// PlaneEmbeddingNetwork fused kernel for GB300 (sm_103a).
// One thread handles one (face, head). Head pair = adjacent lanes (2f, 2f+1).
// All heavy math uses packed fp32 FMA (fma.rn.f32x2) for 2x FFMA throughput.

typedef unsigned long long u64;

__device__ __forceinline__ u64 fma2(u64 a, u64 b, u64 c) {
    u64 d;
    asm("fma.rn.f32x2 %0, %1, %2, %3;" : "=l"(d) : "l"(a), "l"(b), "l"(c));
    return d;
}
__device__ __forceinline__ u64 add2(u64 a, u64 b) {
    u64 d;
    asm("add.rn.f32x2 %0, %1, %2;" : "=l"(d) : "l"(a), "l"(b));
    return d;
}
__device__ __forceinline__ u64 pack2(float x, float y) {
    u64 r;
    asm("mov.b64 %0, {%1, %2};" : "=l"(r) : "f"(x), "f"(y));
    return r;
}
__device__ __forceinline__ float2 unpack2(u64 v) {
    float2 f;
    asm("mov.b64 {%0, %1}, %2;" : "=f"(f.x), "=f"(f.y) : "l"(v));
    return f;
}
__device__ __forceinline__ float getc(float4 v, int c) {
    return c == 0 ? v.x : (c == 1 ? v.y : (c == 2 ? v.z : v.w));
}

// Fused weights computed once by prep kernel:
//   W2[d][j] = sum_e w_out[d][e] * fc_w[e][j]    (16 x 32)
//   b2[j]    = fc_b[j] + sum_e b_out[e] * fc_w[e][j]
__device__ float g_W2[16 * 32];
__device__ float g_b2[32];

__global__ void prep_kernel(const float* __restrict__ w_out, const float* __restrict__ b_out,
                            const float* __restrict__ fc_w, const float* __restrict__ fc_b) {
    int i = threadIdx.x;
    if (i < 512) {
        int d = i >> 5, j = i & 31;
        float s = 0.f;
#pragma unroll
        for (int e = 0; e < 16; e++) s += w_out[d * 16 + e] * fc_w[e * 32 + j];
        g_W2[i] = s;
    }
    if (i < 32) {
        float s = fc_b[i];
#pragma unroll
        for (int e = 0; e < 16; e++) s += b_out[e] * fc_w[e * 32 + i];
        g_b2[i] = s;
    }
}

__global__ void __launch_bounds__(128)
face_kernel(const float* __restrict__ node, const int* __restrict__ fids,
            const float* __restrict__ w_in, const float* __restrict__ b_in,
            const float* __restrict__ fco_w, const float* __restrict__ fco_b,
            float* __restrict__ out, int F) {
    __shared__ __align__(16) float s_win[16 * 48];   // packed qkv weights, row-major [d][o]
    __shared__ __align__(16) float s_bin[48];
    __shared__ __align__(16) float s_W2[16 * 32];    // fused w_out@fc_w
    __shared__ __align__(16) float s_b2[32];
    __shared__ __align__(16) float s_fco[32 * 32];
    __shared__ __align__(16) float s_fcob[32];

    int tid = threadIdx.x;
    for (int i = tid; i < 768; i += 128) s_win[i] = w_in[i];
    if (tid < 48) s_bin[tid] = b_in[tid];
    for (int i = tid; i < 512; i += 128) s_W2[i] = g_W2[i];
    if (tid < 32) s_b2[tid] = g_b2[tid];
    for (int i = tid; i < 1024; i += 128) s_fco[i] = fco_w[i];
    if (tid < 32) s_fcob[tid] = fco_b[tid];
    __syncthreads();

    int gt = blockIdx.x * 128 + tid;
    int face = gt >> 1;
    int h = gt & 1;                 // head index (0 or 1)
    bool valid = face < F;
    if (!valid) face = F - 1;       // clamp: tail lanes still run (shuffle safety), no store

    // ---- gather: 4 edge rows of 16 floats, issued up front for MLP ----
    int4 I = *(const int4*)(fids + 4ll * face);
    int ids[4] = {I.x, I.y, I.z, I.w};
    float4 X[4][4];
#pragma unroll
    for (int t = 0; t < 4; t++) {
        const float4* r = (const float4*)(node + 16ll * ids[t]);
        X[t][0] = r[0]; X[t][1] = r[1]; X[t][2] = r[2]; X[t][3] = r[3];
    }

    // ---- qkv projection for own head: q/k/v[t][0..7] as 4 packed pairs each ----
    u64 q2[4][4], k2[4][4], v2[4][4];
    {
        const u64* bq = (const u64*)(s_bin + 8 * h);
        const u64* bk = (const u64*)(s_bin + 16 + 8 * h);
        const u64* bv = (const u64*)(s_bin + 32 + 8 * h);
#pragma unroll
        for (int t = 0; t < 4; t++)
#pragma unroll
            for (int j = 0; j < 4; j++) { q2[t][j] = bq[j]; k2[t][j] = bk[j]; v2[t][j] = bv[j]; }
    }
    const float* wbase = s_win + 8 * h;
#pragma unroll
    for (int t = 0; t < 4; t++) {
#pragma unroll
        for (int d = 0; d < 16; d++) {
            const float* wd = wbase + d * 48;
            ulonglong2 wq0 = *(const ulonglong2*)(wd);
            ulonglong2 wq1 = *(const ulonglong2*)(wd + 4);
            ulonglong2 wk0 = *(const ulonglong2*)(wd + 16);
            ulonglong2 wk1 = *(const ulonglong2*)(wd + 20);
            ulonglong2 wv0 = *(const ulonglong2*)(wd + 32);
            ulonglong2 wv1 = *(const ulonglong2*)(wd + 36);
            float xv = getc(X[t][d >> 2], d & 3);
            u64 x2 = pack2(xv, xv);
            q2[t][0] = fma2(x2, wq0.x, q2[t][0]); q2[t][1] = fma2(x2, wq0.y, q2[t][1]);
            q2[t][2] = fma2(x2, wq1.x, q2[t][2]); q2[t][3] = fma2(x2, wq1.y, q2[t][3]);
            k2[t][0] = fma2(x2, wk0.x, k2[t][0]); k2[t][1] = fma2(x2, wk0.y, k2[t][1]);
            k2[t][2] = fma2(x2, wk1.x, k2[t][2]); k2[t][3] = fma2(x2, wk1.y, k2[t][3]);
            v2[t][0] = fma2(x2, wv0.x, v2[t][0]); v2[t][1] = fma2(x2, wv0.y, v2[t][1]);
            v2[t][2] = fma2(x2, wv1.x, v2[t][2]); v2[t][3] = fma2(x2, wv1.y, v2[t][3]);
        }
    }

    // ---- scores + softmax (own head, 4x4) ----
    float att[4][4];
    const float RS = 0.35355339059327373f;  // 1/sqrt(8)
#pragma unroll
    for (int qi = 0; qi < 4; qi++) {
#pragma unroll
        for (int ki = 0; ki < 4; ki++) {
            u64 a = fma2(q2[qi][0], k2[ki][0], 0ull);
            a = fma2(q2[qi][1], k2[ki][1], a);
            a = fma2(q2[qi][2], k2[ki][2], a);
            a = fma2(q2[qi][3], k2[ki][3], a);
            float2 p = unpack2(a);
            att[qi][ki] = (p.x + p.y) * RS;
        }
        float m = fmaxf(fmaxf(att[qi][0], att[qi][1]), fmaxf(att[qi][2], att[qi][3]));
        float e0 = __expf(att[qi][0] - m);
        float e1 = __expf(att[qi][1] - m);
        float e2 = __expf(att[qi][2] - m);
        float e3 = __expf(att[qi][3] - m);
        float inv = 1.0f / (e0 + e1 + e2 + e3);
        att[qi][0] = e0 * inv; att[qi][1] = e1 * inv;
        att[qi][2] = e2 * inv; att[qi][3] = e3 * inv;
    }

    // ---- per query token: o = attn @ v (own head 8 dims), partial h = o @ W2_head,
    //      exchange with head partner, relu, accumulate mean-pool ----
    float hsum[32];
#pragma unroll
    for (int j = 0; j < 32; j++) hsum[j] = 0.f;
    const float* W2h = s_W2 + (8 * h) * 32;
    const u64* b2p = (const u64*)s_b2;

#pragma unroll
    for (int qi = 0; qi < 4; qi++) {
        u64 o2[4] = {0ull, 0ull, 0ull, 0ull};
#pragma unroll
        for (int s = 0; s < 4; s++) {
            u64 a2 = pack2(att[qi][s], att[qi][s]);
#pragma unroll
            for (int j = 0; j < 4; j++) o2[j] = fma2(a2, v2[s][j], o2[j]);
        }
        u64 hp[16];
#pragma unroll
        for (int j = 0; j < 16; j++) hp[j] = 0ull;
#pragma unroll
        for (int dl = 0; dl < 8; dl++) {
            float2 op = unpack2(o2[dl >> 1]);
            float od = (dl & 1) ? op.y : op.x;
            u64 od2 = pack2(od, od);
            const ulonglong2* wr = (const ulonglong2*)(W2h + dl * 32);
#pragma unroll
            for (int j4 = 0; j4 < 8; j4++) {
                ulonglong2 w = wr[j4];
                hp[2 * j4]     = fma2(od2, w.x, hp[2 * j4]);
                hp[2 * j4 + 1] = fma2(od2, w.y, hp[2 * j4 + 1]);
            }
        }
        // combine head halves (commutative add -> bit-identical in both lanes)
#pragma unroll
        for (int j2 = 0; j2 < 16; j2++) {
            u64 other = __shfl_xor_sync(0xffffffffu, hp[j2], 1);
            u64 full = add2(add2(hp[j2], other), b2p[j2]);
            float2 f = unpack2(full);
            hsum[2 * j2]     += fmaxf(f.x, 0.f);
            hsum[2 * j2 + 1] += fmaxf(f.y, 0.f);
        }
    }

    // ---- fco: out[16h .. 16h+16) = (hsum/4) @ fco_w + fco_b ----
    u64 acc[8];
    {
        const u64* fb = (const u64*)(s_fcob + 16 * h);
#pragma unroll
        for (int p = 0; p < 8; p++) acc[p] = fb[p];
    }
    const float* fch = s_fco + 16 * h;
#pragma unroll
    for (int e = 0; e < 32; e++) {
        float pe = hsum[e] * 0.25f;
        u64 pe2 = pack2(pe, pe);
        const ulonglong2* fr = (const ulonglong2*)(fch + e * 32);
#pragma unroll
        for (int p4 = 0; p4 < 4; p4++) {
            ulonglong2 w = fr[p4];
            acc[2 * p4]     = fma2(pe2, w.x, acc[2 * p4]);
            acc[2 * p4 + 1] = fma2(pe2, w.y, acc[2 * p4 + 1]);
        }
    }

    if (valid) {
        float* op = out + 32ll * face + 16 * h;
#pragma unroll
        for (int p4 = 0; p4 < 4; p4++) {
            float2 a = unpack2(acc[2 * p4]);
            float2 b = unpack2(acc[2 * p4 + 1]);
            *(float4*)(op + 4 * p4) = make_float4(a.x, a.y, b.x, b.y);
        }
    }
}

extern "C" void kernel_launch(void* const* d_in, const int* in_sizes, int n_in,
                              void* d_out, int out_size) {
    const float* node  = (const float*)d_in[0];
    const int*   fids  = (const int*)d_in[1];
    const float* w_in  = (const float*)d_in[2];
    const float* b_in  = (const float*)d_in[3];
    const float* w_out = (const float*)d_in[4];
    const float* b_out = (const float*)d_in[5];
    const float* fc_w  = (const float*)d_in[6];
    const float* fc_b  = (const float*)d_in[7];
    const float* fco_w = (const float*)d_in[8];
    const float* fco_b = (const float*)d_in[9];

    int F = in_sizes[1] / 4;

    prep_kernel<<<1, 512>>>(w_out, b_out, fc_w, fc_b);

    long long threads = 2ll * F;
    int blocks = (int)((threads + 127) / 128);
    face_kernel<<<blocks, 128>>>(node, fids, w_in, b_in, fco_w, fco_b, (float*)d_out, F);
}

// round 2
// speedup vs baseline: 1.1911x; 1.1911x over previous
#include <cuda_runtime.h>

// PlaneEmbeddingNetwork fused kernel for GB300 (sm_103a), R2.
// 2 threads per face (one per head), adjacent lanes. Lane-local token order:
// lane h gathers tokens {2h, 2h+1}; partner's x scalars arrive via shuffle.
// All GEMM phases use packed fp32 FMA (fma.rn.f32x2) with d-outer loops so
// each shared weight load is amortized over 4 tokens (or 2 tokens / 32 cols).

typedef unsigned long long u64;

__device__ __forceinline__ u64 fma2(u64 a, u64 b, u64 c) {
    u64 d;
    asm("fma.rn.f32x2 %0, %1, %2, %3;" : "=l"(d) : "l"(a), "l"(b), "l"(c));
    return d;
}
__device__ __forceinline__ u64 add2(u64 a, u64 b) {
    u64 d;
    asm("add.rn.f32x2 %0, %1, %2;" : "=l"(d) : "l"(a), "l"(b));
    return d;
}
__device__ __forceinline__ u64 mul2(u64 a, u64 b) {
    u64 d;
    asm("mul.rn.f32x2 %0, %1, %2;" : "=l"(d) : "l"(a), "l"(b));
    return d;
}
__device__ __forceinline__ u64 pack2(float x, float y) {
    u64 r;
    asm("mov.b64 %0, {%1, %2};" : "=l"(r) : "f"(x), "f"(y));
    return r;
}
__device__ __forceinline__ float2 unpack2(u64 v) {
    float2 f;
    asm("mov.b64 {%0, %1}, %2;" : "=f"(f.x), "=f"(f.y) : "l"(v));
    return f;
}
__device__ __forceinline__ float getc(float4 v, int c) {
    return c == 0 ? v.x : (c == 1 ? v.y : (c == 2 ? v.z : v.w));
}

// Fused weights computed once by prep kernel:
//   W2[d][j] = sum_e w_out[d][e] * fc_w[e][j]    (16 x 32)
//   b2[j]    = fc_b[j] + sum_e b_out[e] * fc_w[e][j]
__device__ float g_W2[16 * 32];
__device__ float g_b2[32];

__global__ void prep_kernel(const float* __restrict__ w_out, const float* __restrict__ b_out,
                            const float* __restrict__ fc_w, const float* __restrict__ fc_b) {
    int i = threadIdx.x;
    if (i < 512) {
        int d = i >> 5, j = i & 31;
        float s = 0.f;
#pragma unroll
        for (int e = 0; e < 16; e++) s += w_out[d * 16 + e] * fc_w[e * 32 + j];
        g_W2[i] = s;
    }
    if (i < 32) {
        float s = fc_b[i];
#pragma unroll
        for (int e = 0; e < 16; e++) s += b_out[e] * fc_w[e * 32 + i];
        g_b2[i] = s;
    }
}

__global__ void __launch_bounds__(128, 4)
face_kernel(const float* __restrict__ node, const int* __restrict__ fids,
            const float* __restrict__ w_in, const float* __restrict__ b_in,
            const float* __restrict__ fco_w, const float* __restrict__ fco_b,
            float* __restrict__ out, int F) {
    __shared__ __align__(16) float s_win[16 * 48];   // packed qkv weights [d][o]
    __shared__ __align__(16) float s_bin[48];
    __shared__ __align__(16) float s_W2[16 * 32];    // fused w_out@fc_w
    __shared__ __align__(16) float s_b2[32];
    __shared__ __align__(16) float s_fco[32 * 32];
    __shared__ __align__(16) float s_fcob[32];

    int tid = threadIdx.x;
    for (int i = tid; i < 768; i += 128) s_win[i] = w_in[i];
    if (tid < 48) s_bin[tid] = b_in[tid];
    for (int i = tid; i < 512; i += 128) s_W2[i] = g_W2[i];
    if (tid < 32) s_b2[tid] = g_b2[tid];
    for (int i = tid; i < 1024; i += 128) s_fco[i] = fco_w[i];
    if (tid < 32) s_fcob[tid] = fco_b[tid];
    __syncthreads();

    int gt = blockIdx.x * 128 + tid;
    int face = gt >> 1;
    int h = gt & 1;                 // head index (0 or 1)
    bool valid = face < F;
    if (!valid) face = F - 1;       // clamp: tail lanes still participate in shuffles

    // ---- gather: each lane loads only its OWN 2 tokens (lane-local order) ----
    int4 I = *(const int4*)(fids + 4ll * face);
    int ida = h ? I.z : I.x;
    int idb = h ? I.w : I.y;
    float4 XA[4], XB[4];
    {
        const float4* ra = (const float4*)(node + 16ll * ida);
        const float4* rb = (const float4*)(node + 16ll * idb);
        XA[0] = ra[0]; XA[1] = ra[1]; XA[2] = ra[2]; XA[3] = ra[3];
        XB[0] = rb[0]; XB[1] = rb[1]; XB[2] = rb[2]; XB[3] = rb[3];
    }

    // Lane-local token order: 0 = own_a, 1 = own_b, 2 = partner_a, 3 = partner_b.
    // Attention is permutation-invariant per head, so lanes may disagree on order.

    // ---- phase 1a: q,k for all 4 tokens (own head), d-outer for weight reuse ----
    u64 q2[4][4], k2[4][4];
    {
        const u64* bq = (const u64*)(s_bin + 8 * h);
        const u64* bk = (const u64*)(s_bin + 16 + 8 * h);
#pragma unroll
        for (int t = 0; t < 4; t++)
#pragma unroll
            for (int j = 0; j < 4; j++) { q2[t][j] = bq[j]; k2[t][j] = bk[j]; }
    }
    {
        const float* wq = s_win + 8 * h;
        const float* wk = s_win + 16 + 8 * h;
#pragma unroll
        for (int d = 0; d < 16; d++) {
            ulonglong2 wq0 = *(const ulonglong2*)(wq + d * 48);
            ulonglong2 wq1 = *(const ulonglong2*)(wq + d * 48 + 4);
            ulonglong2 wk0 = *(const ulonglong2*)(wk + d * 48);
            ulonglong2 wk1 = *(const ulonglong2*)(wk + d * 48 + 4);
            float xa = getc(XA[d >> 2], d & 3);
            float xb = getc(XB[d >> 2], d & 3);
            float fa = __shfl_xor_sync(0xffffffffu, xa, 1);
            float fb = __shfl_xor_sync(0xffffffffu, xb, 1);
            u64 xt[4] = {pack2(xa, xa), pack2(xb, xb), pack2(fa, fa), pack2(fb, fb)};
#pragma unroll
            for (int t = 0; t < 4; t++) {
                q2[t][0] = fma2(xt[t], wq0.x, q2[t][0]);
                q2[t][1] = fma2(xt[t], wq0.y, q2[t][1]);
                q2[t][2] = fma2(xt[t], wq1.x, q2[t][2]);
                q2[t][3] = fma2(xt[t], wq1.y, q2[t][3]);
                k2[t][0] = fma2(xt[t], wk0.x, k2[t][0]);
                k2[t][1] = fma2(xt[t], wk0.y, k2[t][1]);
                k2[t][2] = fma2(xt[t], wk1.x, k2[t][2]);
                k2[t][3] = fma2(xt[t], wk1.y, k2[t][3]);
            }
        }
    }

    // ---- scores + softmax (own head, 4x4, lane-local token order) ----
    float att[4][4];
    const float RS = 0.35355339059327373f;  // 1/sqrt(8)
#pragma unroll
    for (int qi = 0; qi < 4; qi++) {
#pragma unroll
        for (int ki = 0; ki < 4; ki++) {
            u64 a = fma2(q2[qi][0], k2[ki][0], 0ull);
            a = fma2(q2[qi][1], k2[ki][1], a);
            a = fma2(q2[qi][2], k2[ki][2], a);
            a = fma2(q2[qi][3], k2[ki][3], a);
            float2 p = unpack2(a);
            att[qi][ki] = (p.x + p.y) * RS;
        }
        float m = fmaxf(fmaxf(att[qi][0], att[qi][1]), fmaxf(att[qi][2], att[qi][3]));
        float e0 = __expf(att[qi][0] - m);
        float e1 = __expf(att[qi][1] - m);
        float e2 = __expf(att[qi][2] - m);
        float e3 = __expf(att[qi][3] - m);
        float inv = 1.0f / (e0 + e1 + e2 + e3);
        att[qi][0] = e0 * inv; att[qi][1] = e1 * inv;
        att[qi][2] = e2 * inv; att[qi][3] = e3 * inv;
    }

    // ---- phase 1b: v for all 4 tokens (own head), d-outer ----
    u64 v2[4][4];
    {
        const u64* bv = (const u64*)(s_bin + 32 + 8 * h);
#pragma unroll
        for (int t = 0; t < 4; t++)
#pragma unroll
            for (int j = 0; j < 4; j++) v2[t][j] = bv[j];
    }
    {
        const float* wv = s_win + 32 + 8 * h;
#pragma unroll
        for (int d = 0; d < 16; d++) {
            ulonglong2 wv0 = *(const ulonglong2*)(wv + d * 48);
            ulonglong2 wv1 = *(const ulonglong2*)(wv + d * 48 + 4);
            float xa = getc(XA[d >> 2], d & 3);
            float xb = getc(XB[d >> 2], d & 3);
            float fa = __shfl_xor_sync(0xffffffffu, xa, 1);
            float fb = __shfl_xor_sync(0xffffffffu, xb, 1);
            u64 xt[4] = {pack2(xa, xa), pack2(xb, xb), pack2(fa, fa), pack2(fb, fb)};
#pragma unroll
            for (int t = 0; t < 4; t++) {
                v2[t][0] = fma2(xt[t], wv0.x, v2[t][0]);
                v2[t][1] = fma2(xt[t], wv0.y, v2[t][1]);
                v2[t][2] = fma2(xt[t], wv1.x, v2[t][2]);
                v2[t][3] = fma2(xt[t], wv1.y, v2[t][3]);
            }
        }
    }

    // ---- o = attn @ v for all 4 local query tokens (own head half: 8 dims) ----
    u64 o2[4][4];
#pragma unroll
    for (int qi = 0; qi < 4; qi++) {
#pragma unroll
        for (int j = 0; j < 4; j++) o2[qi][j] = 0ull;
#pragma unroll
        for (int s = 0; s < 4; s++) {
            u64 a2 = pack2(att[qi][s], att[qi][s]);
#pragma unroll
            for (int j = 0; j < 4; j++) o2[qi][j] = fma2(a2, v2[s][j], o2[qi][j]);
        }
    }

    // ---- exchange o halves: I keep my 2 own tokens, full 16 dims ----
    // My local tokens 2,3 are the partner's own tokens; its local 2,3 are mine.
    u64 olo[2][4], ohi[2][4];   // dims 0-7 and 8-15 of my own 2 tokens
#pragma unroll
    for (int t = 0; t < 2; t++)
#pragma unroll
        for (int j = 0; j < 4; j++) {
            u64 rcv = __shfl_xor_sync(0xffffffffu, o2[t + 2][j], 1);
            u64 own = o2[t][j];
            olo[t][j] = h ? rcv : own;
            ohi[t][j] = h ? own : rcv;
        }

    // ---- W2: h_tok = o_full @ W2 + b2 for my 2 tokens (d-outer, weight reuse) ----
    u64 hA[16], hB[16];
    {
        const u64* b2p = (const u64*)s_b2;
#pragma unroll
        for (int j = 0; j < 16; j++) { hA[j] = b2p[j]; hB[j] = b2p[j]; }
    }
#pragma unroll
    for (int d = 0; d < 8; d++) {
        const ulonglong2* wr = (const ulonglong2*)(s_W2 + d * 32);
        float2 pa = unpack2(olo[0][d >> 1]);
        float2 pb = unpack2(olo[1][d >> 1]);
        float x0 = (d & 1) ? pa.y : pa.x;
        float x1 = (d & 1) ? pb.y : pb.x;
        u64 x0p = pack2(x0, x0), x1p = pack2(x1, x1);
#pragma unroll
        for (int j4 = 0; j4 < 8; j4++) {
            ulonglong2 w = wr[j4];
            hA[2 * j4]     = fma2(x0p, w.x, hA[2 * j4]);
            hA[2 * j4 + 1] = fma2(x0p, w.y, hA[2 * j4 + 1]);
            hB[2 * j4]     = fma2(x1p, w.x, hB[2 * j4]);
            hB[2 * j4 + 1] = fma2(x1p, w.y, hB[2 * j4 + 1]);
        }
    }
#pragma unroll
    for (int d = 8; d < 16; d++) {
        const ulonglong2* wr = (const ulonglong2*)(s_W2 + d * 32);
        float2 pa = unpack2(ohi[0][(d - 8) >> 1]);
        float2 pb = unpack2(ohi[1][(d - 8) >> 1]);
        float x0 = (d & 1) ? pa.y : pa.x;
        float x1 = (d & 1) ? pb.y : pb.x;
        u64 x0p = pack2(x0, x0), x1p = pack2(x1, x1);
#pragma unroll
        for (int j4 = 0; j4 < 8; j4++) {
            ulonglong2 w = wr[j4];
            hA[2 * j4]     = fma2(x0p, w.x, hA[2 * j4]);
            hA[2 * j4 + 1] = fma2(x0p, w.y, hA[2 * j4 + 1]);
            hB[2 * j4]     = fma2(x1p, w.x, hB[2 * j4]);
            hB[2 * j4 + 1] = fma2(x1p, w.y, hB[2 * j4 + 1]);
        }
    }

    // ---- relu + pool over my 2 tokens, exchange partial sums, scale by 1/4 ----
    u64 pool[16];
    const u64 QUARTER = pack2(0.25f, 0.25f);
#pragma unroll
    for (int j = 0; j < 16; j++) {
        float2 a = unpack2(hA[j]);
        float2 b = unpack2(hB[j]);
        float px = fmaxf(a.x, 0.f) + fmaxf(b.x, 0.f);
        float py = fmaxf(a.y, 0.f) + fmaxf(b.y, 0.f);
        u64 p = pack2(px, py);
        u64 q = __shfl_xor_sync(0xffffffffu, p, 1);
        pool[j] = mul2(add2(p, q), QUARTER);   // commutative add -> identical both lanes
    }

    // ---- fco: out[16h .. 16h+16) = pooled @ fco_w + fco_b ----
    u64 acc[8];
    {
        const u64* fb = (const u64*)(s_fcob + 16 * h);
#pragma unroll
        for (int p = 0; p < 8; p++) acc[p] = fb[p];
    }
    const float* fch = s_fco + 16 * h;
#pragma unroll
    for (int e = 0; e < 32; e++) {
        float2 pp = unpack2(pool[e >> 1]);
        float pe = (e & 1) ? pp.y : pp.x;
        u64 pe2 = pack2(pe, pe);
        const ulonglong2* fr = (const ulonglong2*)(fch + e * 32);
#pragma unroll
        for (int p4 = 0; p4 < 4; p4++) {
            ulonglong2 w = fr[p4];
            acc[2 * p4]     = fma2(pe2, w.x, acc[2 * p4]);
            acc[2 * p4 + 1] = fma2(pe2, w.y, acc[2 * p4 + 1]);
        }
    }

    if (valid) {
        float* op = out + 32ll * face + 16 * h;
#pragma unroll
        for (int p4 = 0; p4 < 4; p4++) {
            float2 a = unpack2(acc[2 * p4]);
            float2 b = unpack2(acc[2 * p4 + 1]);
            *(float4*)(op + 4 * p4) = make_float4(a.x, a.y, b.x, b.y);
        }
    }
}

extern "C" void kernel_launch(void* const* d_in, const int* in_sizes, int n_in,
                              void* d_out, int out_size) {
    const float* node  = (const float*)d_in[0];
    const int*   fids  = (const int*)d_in[1];
    const float* w_in  = (const float*)d_in[2];
    const float* b_in  = (const float*)d_in[3];
    const float* w_out = (const float*)d_in[4];
    const float* b_out = (const float*)d_in[5];
    const float* fc_w  = (const float*)d_in[6];
    const float* fc_b  = (const float*)d_in[7];
    const float* fco_w = (const float*)d_in[8];
    const float* fco_b = (const float*)d_in[9];

    int F = in_sizes[1] / 4;

    prep_kernel<<<1, 512>>>(w_out, b_out, fc_w, fc_b);

    long long threads = 2ll * F;
    int blocks = (int)((threads + 127) / 128);
    face_kernel<<<blocks, 128>>>(node, fids, w_in, b_in, fco_w, fco_b, (float*)d_out, F);
}